// round 5
// baseline (speedup 1.0000x reference)
#include <cuda_runtime.h>
#include <cuda_fp16.h>
#include <math.h>

#define GX 128
#define GY 128
#define GZ 128
#define VDIM 28
#define NUM_RAYS 8192
#define NUM_SAMPLES 128
#define NVOX (GX*GY*GZ)

// Reduced grid in [x][z][y] layout. Entry e = x*16384 + z*128 + y holds fp16
// (sigma,r,g,b) for voxel (x,y,z) AND voxel (x,y,z+1) (z-pair) in 16 B.
// y is the fastest dimension so the two y-corners of a sample are ADJACENT
// entries -> a lane pair loading them coalesces into one 128B-line wavefront.
__device__ uint4 g_pairs[NVOX];

// ---------------------------------------------------------------------------
// SH basis (degree 2), reference coefficient order.
// ---------------------------------------------------------------------------
__device__ __forceinline__ void sh_basis9(const float* __restrict__ ang, float* b) {
    float theta = ang[0], phi = ang[1];
    float st, ct, sp, cp;
    __sincosf(theta, &st, &ct);
    __sincosf(phi, &sp, &cp);
    const float y00 = 0.28209479177387814f;
    const float h3  = 0.4886025119029199f;
    const float q5  = 0.31539156525252005f;
    const float h15 = 1.0925484305920792f;
    const float q15 = 0.5462742152960396f;
    b[0] = y00;
    b[1] = h3 * st * sp;
    b[2] = h3 * ct;
    b[3] = h3 * st * cp;
    b[4] = h15 * st * cp * st * sp;
    b[5] = h15 * st * sp * ct;
    b[6] = q5 * (3.0f * ct * ct - 1.0f);
    b[7] = h15 * st * cp * ct;
    b[8] = q15 * ((st * cp) * (st * cp) - (st * sp) * (st * sp));
}

__device__ __forceinline__ uint2 contract_voxel(const float* __restrict__ grid,
                                                const float* __restrict__ b, int v) {
    const float4* vp = (const float4*)(grid + (size_t)v * VDIM);
    float f[VDIM];
    #pragma unroll
    for (int i = 0; i < 7; i++) {
        float4 t = __ldcs(vp + i);
        f[i*4+0] = t.x; f[i*4+1] = t.y; f[i*4+2] = t.z; f[i*4+3] = t.w;
    }
    float r = 0.f, g = 0.f, bl = 0.f;
    #pragma unroll
    for (int k = 0; k < 9; k++) {
        r  = fmaf(f[1  + k], b[k], r);
        g  = fmaf(f[10 + k], b[k], g);
        bl = fmaf(f[19 + k], b[k], bl);
    }
    __half2 h0 = __floats2half2_rn(f[0], r);
    __half2 h1 = __floats2half2_rn(g, bl);
    uint2 u;
    u.x = *(const unsigned int*)&h0;
    u.y = *(const unsigned int*)&h1;
    return u;
}

// ---------------------------------------------------------------------------
// Kernel 1: contract + z-pair, writing the transposed [x][z][y] layout via a
// smem tile so stores remain full-line coalesced.
// Block tile: fixed x, 8 y-values x 32 z-values (+ z halo column).
// ---------------------------------------------------------------------------
__global__ __launch_bounds__(256) void reduce_kernel(
    const float* __restrict__ grid, const float* __restrict__ ang)
{
    __shared__ uint2 s[8][33];
    float b[9];
    sh_basis9(ang, b);

    int t = threadIdx.x;
    int blk = blockIdx.x;          // 128 x * 16 ytiles * 4 ztiles = 8192
    int x  = blk >> 6;
    int yt = (blk >> 2) & 15;
    int zt = blk & 3;
    int y0 = yt << 3, z0 = zt << 5;

    int ty = t >> 5, tz = t & 31;  // read mapping: warp = one y row, 32 consec z
    int v = (x << 14) | ((y0 + ty) << 7) | (z0 + tz);
    s[ty][tz] = contract_voxel(grid, b, v);
    if (t < 8) {                   // z halo (content for entries at z0+31)
        int zh = z0 + 32; if (zh > 127) zh = 127;   // clamped value never read
        int vh = (x << 14) | ((y0 + t) << 7) | zh;
        s[t][32] = contract_voxel(grid, b, vh);
    }
    __syncthreads();

    int wz = t >> 3, wy = t & 7;   // write mapping: y fastest -> coalesced
    uint2 a = s[wy][wz], c = s[wy][wz + 1];
    int e = (x << 14) + ((z0 + wz) << 7) + (y0 + wy);
    g_pairs[e] = make_uint4(a.x, a.y, c.x, c.y);
}

// ---------------------------------------------------------------------------
// Kernel 2: rendering. 2 lanes per sample (lane parity = y-corner),
// 16 samples per warp, 8 warps = 1 ray per 256-thread block.
// ---------------------------------------------------------------------------
__device__ __forceinline__ float4 zlerp_pair(uint4 t, float zd) {
    float2 a0 = __half22float2(*(__half2*)&t.x);
    float2 a1 = __half22float2(*(__half2*)&t.y);
    float2 b0 = __half22float2(*(__half2*)&t.z);
    float2 b1 = __half22float2(*(__half2*)&t.w);
    return make_float4(fmaf(b0.x - a0.x, zd, a0.x),
                       fmaf(b0.y - a0.y, zd, a0.y),
                       fmaf(b1.x - a1.x, zd, a1.x),
                       fmaf(b1.y - a1.y, zd, a1.y));
}

__device__ __forceinline__ float ylerp1(float mine, int ly, float yd) {
    float oth = __shfl_xor_sync(0xffffffffu, mine, 1);
    float a = ly ? oth : mine;   // y0 value
    float b = ly ? mine : oth;   // y1 value
    return fmaf(b - a, yd, a);
}

__global__ __launch_bounds__(256) void render_kernel(
    const float* __restrict__ pos, const float* __restrict__ dist,
    float* __restrict__ out)
{
    __shared__ float s_wsum[8];
    __shared__ float s_acc[8][3];

    int ray  = blockIdx.x;
    int tid  = threadIdx.x;
    int wid  = tid >> 5;
    int lane = tid & 31;
    int p    = lane >> 1;         // sample within warp: 0..15
    int ly   = lane & 1;          // which y-corner this lane owns
    int s    = (wid << 4) + p;    // sample within ray: 0..127

    const float* pp = pos + (size_t)ray * (NUM_SAMPLES * 3) + s * 3;
    float x = pp[0], y = pp[1], z = pp[2];
    float d = dist[(size_t)ray * NUM_SAMPLES + s];

    int xi = (int)x, yi = (int)y, zi = (int)z;   // in [0,126]
    float xd = x - (float)xi, yd = y - (float)yi, zd = z - (float)zi;

    int e = (xi << 14) + (zi << 7) + yi + ly;
    uint4 A = __ldcg(&g_pairs[e]);           // x = xi   side
    uint4 B = __ldcg(&g_pairs[e + 16384]);   // x = xi+1 side

    float4 va = zlerp_pair(A, zd);
    float4 vb = zlerp_pair(B, zd);
    float4 v = make_float4(fmaf(vb.x - va.x, xd, va.x),
                           fmaf(vb.y - va.y, xd, va.y),
                           fmaf(vb.z - va.z, xd, va.z),
                           fmaf(vb.w - va.w, xd, va.w));

    // y-lerp across the lane pair (both lanes end with the full sample value)
    float sig = ylerp1(v.x, ly, yd);
    float rr  = ylerp1(v.y, ly, yd);
    float gg  = ylerp1(v.z, ly, yd);
    float bb  = ylerp1(v.w, ly, yd);

    float att = __expf(-sig * d);

    // Inclusive cumsum of att over the ray. Samples are duplicated in lane
    // pairs; compact to 16-lane groups, scan, then read back per-lane.
    float att_s = __shfl_sync(0xffffffffu, att, (lane & 15) << 1);
    float inc = att_s;
    #pragma unroll
    for (int o = 1; o < 16; o <<= 1) {
        float n = __shfl_up_sync(0xffffffffu, inc, o);
        if ((lane & 15) >= o) inc += n;
    }
    float inc_mine = __shfl_sync(0xffffffffu, inc, p);
    float wtot     = __shfl_sync(0xffffffffu, inc, 15);
    if (lane == 0) s_wsum[wid] = wtot;
    __syncthreads();
    float off = 0.f;
    #pragma unroll
    for (int w = 0; w < 7; w++)
        if (w < wid) off += s_wsum[w];
    float T = off + inc_mine;

    float w = T * (1.0f - att);
    float ar = w * rr, ag = w * gg, ab = w * bb;

    #pragma unroll
    for (int o = 16; o > 0; o >>= 1) {
        ar += __shfl_xor_sync(0xffffffffu, ar, o);
        ag += __shfl_xor_sync(0xffffffffu, ag, o);
        ab += __shfl_xor_sync(0xffffffffu, ab, o);
    }
    if (lane == 0) {               // each sample counted twice -> x0.5 (exact)
        s_acc[wid][0] = 0.5f * ar;
        s_acc[wid][1] = 0.5f * ag;
        s_acc[wid][2] = 0.5f * ab;
    }
    __syncthreads();
    if (tid < 3) {
        float acc = 0.f;
        #pragma unroll
        for (int wv = 0; wv < 8; wv++) acc += s_acc[wv][tid];
        out[ray * 3 + tid] = acc;
    }
}

extern "C" void kernel_launch(void* const* d_in, const int* in_sizes, int n_in,
                              void* d_out, int out_size) {
    const float* voxel_grid = (const float*)d_in[0];
    const float* sample_positions = (const float*)d_in[1];
    const float* sample_distances = (const float*)d_in[2];
    const float* viewing_angle = (const float*)d_in[3];
    float* out = (float*)d_out;

    reduce_kernel<<<8192, 256>>>(voxel_grid, viewing_angle);
    render_kernel<<<NUM_RAYS, 256>>>(sample_positions, sample_distances, out);
}